// round 3
// baseline (speedup 1.0000x reference)
#include <cuda_runtime.h>
#include <cstdint>

// ---------------------------------------------------------------------------
// StreamingMultiScaleTCN fused kernel (tf32 mma.sync formulation)
//
// Branches (padded to 9 taps each, zero weights for missing leading taps):
//   br0: K=3, d=1   br1: K=5, d=2   br2: K=9, d=4   br3: K=9, d=8
// y[t] = sum_{j=0..8} wpad[j] * x[t - d*(8-j)]   (causal; max lookback 64)
// Taps with all-zero padded weights are skipped in the MMA stage (identical
// result, ~28% less tensor work).
//
// Per block: one batch b, 128 timesteps. Stages:
//   A: x[t0-64 .. t0+128) x 64ch -> smem (tf32)
//   B: 9 taps x GEMM(128t x 128c x 64ci) via m16n8k8.tf32; warp=(branch,thalf)
//      weight slab (4br x 64 x 32 per tap) double-buffered with cp.async
//   relu+bias -> act smem (tf32)
//   C: out = act @ w_out (128x128x128) + b_out -> gmem
// ---------------------------------------------------------------------------

#define XS_LD  68    // 192-row x tile, padded stride
#define ACT_LD 132   // 128-row act tile
#define WS_LD  40    // tap slab [4][64][40]
#define WO_LD  136   // w_out [128][136]

#define SMEM_FLOATS (192*XS_LD + 128*ACT_LD + 2*4*64*WS_LD)
#define SMEM_BYTES  (SMEM_FLOATS * 4)

__device__ float g_wpad[4*9*64*32];   // packed, zero-padded, tf32-rounded
__device__ float g_bcat[128];         // concat branch biases

__device__ __forceinline__ float to_tf32(float x) {
    uint32_t r;
    asm("cvt.rna.tf32.f32 %0, %1;" : "=r"(r) : "f"(x));   // tf32 dst is .b32
    return __uint_as_float(r);
}

__device__ __forceinline__ void mma8(float* d, const uint32_t* a, const uint32_t* b) {
    asm volatile(
        "mma.sync.aligned.m16n8k8.row.col.f32.tf32.tf32.f32 "
        "{%0,%1,%2,%3}, {%4,%5,%6,%7}, {%8,%9}, {%0,%1,%2,%3};\n"
        : "+f"(d[0]), "+f"(d[1]), "+f"(d[2]), "+f"(d[3])
        : "r"(a[0]), "r"(a[1]), "r"(a[2]), "r"(a[3]),
          "r"(b[0]), "r"(b[1]));
}

__device__ __forceinline__ void cp_async16(void* dst, const void* src) {
    uint32_t s = (uint32_t)__cvta_generic_to_shared(dst);
    asm volatile("cp.async.cg.shared.global [%0], [%1], 16;\n" :: "r"(s), "l"(src));
}
__device__ __forceinline__ void cp_commit() { asm volatile("cp.async.commit_group;\n"); }
template <int N>
__device__ __forceinline__ void cp_wait() { asm volatile("cp.async.wait_group %0;\n" :: "n"(N)); }

// --------------------------- weight prep kernel -----------------------------
__global__ void prep_kernel(const float* __restrict__ w_s, const float* __restrict__ w_m,
                            const float* __restrict__ w_l, const float* __restrict__ w_xl,
                            const float* __restrict__ b_s, const float* __restrict__ b_m,
                            const float* __restrict__ b_l, const float* __restrict__ b_xl) {
    int idx = blockIdx.x * 256 + threadIdx.x;
    if (idx < 4*9*64*32) {
        int c  = idx & 31;
        int ci = (idx >> 5) & 63;
        int bj = idx >> 11;        // br*9 + j
        int j  = bj % 9;
        int br = bj / 9;
        float v = 0.f;
        if      (br == 0) { if (j >= 6) v = w_s [((j-6)*64 + ci)*32 + c]; }  // K=3
        else if (br == 1) { if (j >= 4) v = w_m [((j-4)*64 + ci)*32 + c]; }  // K=5
        else if (br == 2) {             v = w_l [(j    *64 + ci)*32 + c]; }  // K=9
        else              {             v = w_xl[(j    *64 + ci)*32 + c]; }  // K=9
        g_wpad[idx] = to_tf32(v);
    }
    if (blockIdx.x == 0 && threadIdx.x < 128) {
        int i = threadIdx.x;
        const float* bsel = (i < 32) ? b_s : (i < 64) ? b_m : (i < 96) ? b_l : b_xl;
        g_bcat[i] = bsel[i & 31];
    }
}

// ------------------------------ main kernel ---------------------------------
__global__ __launch_bounds__(256, 1)
void tcn_kernel(const float* __restrict__ x, const float* __restrict__ w_out,
                const float* __restrict__ b_out, float* __restrict__ out) {
    extern __shared__ float smem[];
    float* xs  = smem;                    // [192][68]
    float* act = xs + 192*XS_LD;          // [128][132]
    float* ws  = act + 128*ACT_LD;        // 2x tap slab; later w_out [128][136]

    const int tid  = threadIdx.x;
    const int lane = tid & 31;
    const int wrp  = tid >> 5;
    const int g    = lane >> 2;   // 0..7
    const int tg   = lane & 3;    // 0..3
    const int b    = blockIdx.y;
    const int t0   = blockIdx.x * 128;

    // ---- slab prologue: tap 0 weights via cp.async (overlaps stage A) ----
    {
        int br2 = tid >> 6, ci = tid & 63;
        const float* src = g_wpad + ((br2*9 + 0)*64 + ci)*32;
        float* dst = ws + (br2*64 + ci)*WS_LD;
        #pragma unroll
        for (int q = 0; q < 8; q++) cp_async16(dst + q*4, src + q*4);
    }
    cp_commit();

    // ---- Stage A: x tile (with 64-row causal halo) -> smem, tf32 ----
    {
        const float* xb = x + ((size_t)b * 8192) * 64;
        #pragma unroll 4
        for (int i = tid; i < 192*16; i += 256) {
            int r = i >> 4, q = i & 15;
            int gt = t0 - 64 + r;
            float4 v = make_float4(0.f, 0.f, 0.f, 0.f);
            if (gt >= 0) v = *(const float4*)(xb + (size_t)gt*64 + q*4);
            v.x = to_tf32(v.x); v.y = to_tf32(v.y);
            v.z = to_tf32(v.z); v.w = to_tf32(v.w);
            *(float4*)(xs + r*XS_LD + q*4) = v;
        }
    }

    const int br    = wrp >> 1;     // branch (warp-uniform)
    const int thalf = wrp & 1;      // t half
    const int dil   = 1 << br;      // 1,2,4,8
    const int jmin  = (br == 0) ? 6 : (br == 1) ? 4 : 0;  // first nonzero tap

    float acc[4][4][4];
    #pragma unroll
    for (int mt = 0; mt < 4; mt++)
        #pragma unroll
        for (int nt = 0; nt < 4; nt++)
            #pragma unroll
            for (int r = 0; r < 4; r++) acc[mt][nt][r] = 0.f;

    // ---- Stage B: 9 taps, each a 128x128x64 GEMM; warp tile 64t x 32c ----
    for (int j = 0; j < 9; j++) {
        if (j < 8) {  // prefetch next tap slab into the other buffer
            int br2 = tid >> 6, ci = tid & 63;
            const float* src = g_wpad + ((br2*9 + (j+1))*64 + ci)*32;
            float* dst = ws + ((j+1)&1)*(4*64*WS_LD) + (br2*64 + ci)*WS_LD;
            #pragma unroll
            for (int q = 0; q < 8; q++) cp_async16(dst + q*4, src + q*4);
            cp_commit();
            cp_wait<1>();   // tap j complete (one newer group may be pending)
        } else {
            cp_wait<0>();
        }
        __syncthreads();   // slab j visible to all; stage A done (j==0)

        if (j >= jmin) {   // padded taps are all-zero weights: skip (no-op adds)
            const uint32_t* S = (const uint32_t*)(ws + (j&1)*(4*64*WS_LD) + br*64*WS_LD);
            const int off   = dil * (8 - j);
            const int arow0 = 64 + thalf*64 + g - off;

            #pragma unroll
            for (int ks = 0; ks < 8; ks++) {
                const int ci0 = ks * 8;
                uint32_t a[4][4];
                #pragma unroll
                for (int mt = 0; mt < 4; mt++) {
                    const uint32_t* xp = (const uint32_t*)xs + (arow0 + mt*16)*XS_LD + ci0 + tg;
                    a[mt][0] = xp[0];
                    a[mt][1] = xp[8*XS_LD];
                    a[mt][2] = xp[4];
                    a[mt][3] = xp[8*XS_LD + 4];
                }
                uint32_t bb[4][2];
                #pragma unroll
                for (int nt = 0; nt < 4; nt++) {
                    const uint32_t* wp = S + (ci0 + tg)*WS_LD + nt*8 + g;
                    bb[nt][0] = wp[0];
                    bb[nt][1] = wp[4*WS_LD];
                }
                #pragma unroll
                for (int mt = 0; mt < 4; mt++)
                    #pragma unroll
                    for (int nt = 0; nt < 4; nt++)
                        mma8(acc[mt][nt], a[mt], bb[nt]);
            }
        }
        __syncthreads();   // all readers done before next prefetch overwrites
    }

    // ---- bias + relu -> act smem (tf32) ----
    {
        #pragma unroll
        for (int nt = 0; nt < 4; nt++) {
            int c = br*32 + nt*8 + 2*tg;
            float2 bv = *(const float2*)(g_bcat + c);
            #pragma unroll
            for (int mt = 0; mt < 4; mt++) {
                int r0 = thalf*64 + mt*16 + g;
                float v0 = fmaxf(acc[mt][nt][0] + bv.x, 0.f);
                float v1 = fmaxf(acc[mt][nt][1] + bv.y, 0.f);
                float v2 = fmaxf(acc[mt][nt][2] + bv.x, 0.f);
                float v3 = fmaxf(acc[mt][nt][3] + bv.y, 0.f);
                *(float2*)(act + (size_t)r0*ACT_LD + c)     = make_float2(to_tf32(v0), to_tf32(v1));
                *(float2*)(act + (size_t)(r0+8)*ACT_LD + c) = make_float2(to_tf32(v2), to_tf32(v3));
            }
        }
    }
    __syncthreads();

    // ---- stage w_out into smem (overlays tap slabs), tf32, [128][136] ----
    {
        #pragma unroll 4
        for (int i = tid; i < 128*32; i += 256) {
            int r = i >> 5, q = i & 31;
            float4 v = *(const float4*)(w_out + r*128 + q*4);
            v.x = to_tf32(v.x); v.y = to_tf32(v.y);
            v.z = to_tf32(v.z); v.w = to_tf32(v.w);
            *(float4*)(ws + r*WO_LD + q*4) = v;
        }
    }
    __syncthreads();

    // ---- Stage C: out = relu_act @ w_out + b_out (128x128x128) ----
    const int mq = wrp >> 2;   // t half
    const int nq = wrp & 3;    // f quarter
    #pragma unroll
    for (int mt = 0; mt < 4; mt++)
        #pragma unroll
        for (int nt = 0; nt < 4; nt++)
            #pragma unroll
            for (int r = 0; r < 4; r++) acc[mt][nt][r] = 0.f;

    #pragma unroll
    for (int ks = 0; ks < 16; ks++) {
        const int ci0 = ks * 8;
        uint32_t a[4][4];
        #pragma unroll
        for (int mt = 0; mt < 4; mt++) {
            const uint32_t* ap = (const uint32_t*)act + (mq*64 + mt*16 + g)*ACT_LD + ci0 + tg;
            a[mt][0] = ap[0];
            a[mt][1] = ap[8*ACT_LD];
            a[mt][2] = ap[4];
            a[mt][3] = ap[8*ACT_LD + 4];
        }
        uint32_t bb[4][2];
        #pragma unroll
        for (int nt = 0; nt < 4; nt++) {
            const uint32_t* wp = (const uint32_t*)ws + (ci0 + tg)*WO_LD + nq*32 + nt*8 + g;
            bb[nt][0] = wp[0];
            bb[nt][1] = wp[4*WO_LD];
        }
        #pragma unroll
        for (int mt = 0; mt < 4; mt++)
            #pragma unroll
            for (int nt = 0; nt < 4; nt++)
                mma8(acc[mt][nt], a[mt], bb[nt]);
    }

    // ---- epilogue: + b_out, store ----
    {
        float* ob = out + ((size_t)b*8192 + t0) * 128;
        #pragma unroll
        for (int nt = 0; nt < 4; nt++) {
            int c = nq*32 + nt*8 + 2*tg;
            float2 bv = *(const float2*)(b_out + c);
            #pragma unroll
            for (int mt = 0; mt < 4; mt++) {
                int r0 = mq*64 + mt*16 + g;
                *(float2*)(ob + (size_t)r0*128 + c) =
                    make_float2(acc[mt][nt][0] + bv.x, acc[mt][nt][1] + bv.y);
                *(float2*)(ob + (size_t)(r0+8)*128 + c) =
                    make_float2(acc[mt][nt][2] + bv.x, acc[mt][nt][3] + bv.y);
            }
        }
    }
}

// ------------------------------ launcher ------------------------------------
extern "C" void kernel_launch(void* const* d_in, const int* in_sizes, int n_in,
                              void* d_out, int out_size) {
    const float* x     = (const float*)d_in[0];
    const float* w_s   = (const float*)d_in[1];
    const float* b_s   = (const float*)d_in[2];
    const float* w_m   = (const float*)d_in[3];
    const float* b_m   = (const float*)d_in[4];
    const float* w_l   = (const float*)d_in[5];
    const float* b_l   = (const float*)d_in[6];
    const float* w_xl  = (const float*)d_in[7];
    const float* b_xl  = (const float*)d_in[8];
    const float* w_out = (const float*)d_in[9];
    const float* b_out = (const float*)d_in[10];
    float* out = (float*)d_out;

    cudaFuncSetAttribute(tcn_kernel, cudaFuncAttributeMaxDynamicSharedMemorySize, SMEM_BYTES);

    prep_kernel<<<288, 256>>>(w_s, w_m, w_l, w_xl, b_s, b_m, b_l, b_xl);

    dim3 grid(8192 / 128, 16);   // (t-tiles, batch)
    tcn_kernel<<<grid, 256, SMEM_BYTES>>>(x, w_out, b_out, out);
}

// round 6
// speedup vs baseline: 1.7818x; 1.7818x over previous
#include <cuda_runtime.h>
#include <cstdint>

// ---------------------------------------------------------------------------
// StreamingMultiScaleTCN fused kernel, R6 (= R5 resubmit; R5 hit an infra
// failure and never ran). Fragment-packed weights via LDG, barrier-free conv
// stage, 2 CTAs/SM, ACT_LD=132.
//
// y[t] = sum_j w[j] * x[t - d*(K-1-j)]  per branch; branches
//   br0: K=3,d=1  br1: K=5,d=2  br2: K=9,d=4  br3: K=9,d=8
// Then relu(y+b), concat(128), 1x1 proj via w_out.
//
// Per CTA: one batch b, 128 timesteps.
//   A: x[t0-64 .. t0+128) x 64ch -> smem xs (tf32)       [syncthreads]
//   B: per-warp (branch, t-half) conv GEMMs, m16n8k8.tf32; B-operands are
//      pre-packed fragment streams (g_wfrag) via coalesced LDG.128 — no smem
//      staging, no barriers, no cross-branch lockstep     [syncthreads]
//   relu+bias -> act smem (overlays xs)                   [syncthreads]
//   C: out = act @ w_out + b_out; w_out fragments via LDG.128 (g_wofrag)
// ---------------------------------------------------------------------------

#define XS_LD  68    // (4t+ci)%32 distinct across lanes; 192*68 = 13056 floats
#define ACT_LD 132   // >=128 cols + pad; 132%32==4 keeps reads conflict-free

#define SMEM_FLOATS (128 * ACT_LD)            // 16896 >= 192*XS_LD (overlay ok)
#define SMEM_BYTES  (SMEM_FLOATS * 4)         // 67584 B -> 2 CTAs/SM

#define CONV_WORDS (4*9*8*32*8)   // [br][tap][ks][lane][8w] = 73728
#define WO_WORDS   (4*16*32*8)    // [nq][ks][lane][8w]      = 16384

__device__ __align__(16) float g_wfrag[CONV_WORDS];  // conv B-fragments, tf32
__device__ __align__(16) float g_wofrag[WO_WORDS];   // w_out B-fragments, tf32
__device__ float g_bcat[128];                        // concat branch biases

__device__ __forceinline__ float to_tf32(float x) {
    uint32_t r;
    asm("cvt.rna.tf32.f32 %0, %1;" : "=r"(r) : "f"(x));
    return __uint_as_float(r);
}

__device__ __forceinline__ void mma8(float* d, const uint32_t* a, const uint32_t* b) {
    asm volatile(
        "mma.sync.aligned.m16n8k8.row.col.f32.tf32.tf32.f32 "
        "{%0,%1,%2,%3}, {%4,%5,%6,%7}, {%8,%9}, {%0,%1,%2,%3};\n"
        : "+f"(d[0]), "+f"(d[1]), "+f"(d[2]), "+f"(d[3])
        : "r"(a[0]), "r"(a[1]), "r"(a[2]), "r"(a[3]),
          "r"(b[0]), "r"(b[1]));
}

// --------------------------- weight prep kernel -----------------------------
// Fragment layout (m16n8k8 col-major B):
//   word w in [0,8): nt = w>>1, half = w&1
//   ci = ks*8 + (lane&3) + 4*half ; c (out col in 32) = (w>>1)*8 + (lane>>2)
__global__ void prep_kernel(const float* __restrict__ w_s, const float* __restrict__ w_m,
                            const float* __restrict__ w_l, const float* __restrict__ w_xl,
                            const float* __restrict__ b_s, const float* __restrict__ b_m,
                            const float* __restrict__ b_l, const float* __restrict__ b_xl,
                            const float* __restrict__ w_out) {
    int idx = blockIdx.x * 256 + threadIdx.x;
    if (idx < CONV_WORDS) {
        int w    = idx & 7;
        int lane = (idx >> 3) & 31;
        int ks   = (idx >> 8) & 7;
        int bj   = idx >> 11;          // br*9 + j
        int j    = bj % 9;
        int br   = bj / 9;
        int ci   = ks*8 + (lane & 3) + 4*(w & 1);
        int c    = (w >> 1)*8 + (lane >> 2);
        float v = 0.f;
        if      (br == 0) { if (j >= 6) v = w_s [((j-6)*64 + ci)*32 + c]; }  // K=3
        else if (br == 1) { if (j >= 4) v = w_m [((j-4)*64 + ci)*32 + c]; }  // K=5
        else if (br == 2) {             v = w_l [(j    *64 + ci)*32 + c]; }  // K=9
        else              {             v = w_xl[(j    *64 + ci)*32 + c]; }  // K=9
        g_wfrag[idx] = to_tf32(v);
    } else if (idx < CONV_WORDS + WO_WORDS) {
        int k    = idx - CONV_WORDS;
        int w    = k & 7;
        int lane = (k >> 3) & 31;
        int ks   = (k >> 8) & 15;
        int nq   = k >> 12;
        int ci   = ks*8 + (lane & 3) + 4*(w & 1);
        int f    = nq*32 + (w >> 1)*8 + (lane >> 2);
        g_wofrag[k] = to_tf32(w_out[ci*128 + f]);
    }
    if (blockIdx.x == 0 && threadIdx.x < 128) {
        int i = threadIdx.x;
        const float* bsel = (i < 32) ? b_s : (i < 64) ? b_m : (i < 96) ? b_l : b_xl;
        g_bcat[i] = bsel[i & 31];
    }
}

// ------------------------------ main kernel ---------------------------------
__global__ __launch_bounds__(256, 2)
void tcn_kernel(const float* __restrict__ x,
                const float* __restrict__ b_out, float* __restrict__ out) {
    extern __shared__ float smem[];
    float* xs  = smem;   // [192][68] during stages A/B
    float* act = smem;   // [128][132] overlays xs after stage B

    const int tid  = threadIdx.x;
    const int lane = tid & 31;
    const int wrp  = tid >> 5;
    const int g    = lane >> 2;   // 0..7
    const int tg   = lane & 3;    // 0..3
    const int b    = blockIdx.y;
    const int t0   = blockIdx.x * 128;

    // ---- Stage A: x tile (with 64-row causal halo) -> smem, tf32 ----
    {
        const float* xb = x + ((size_t)b * 8192) * 64;
        #pragma unroll 4
        for (int i = tid; i < 192*16; i += 256) {
            int r = i >> 4, q = i & 15;
            int gt = t0 - 64 + r;
            float4 v = make_float4(0.f, 0.f, 0.f, 0.f);
            if (gt >= 0) v = *(const float4*)(xb + (size_t)gt*64 + q*4);
            v.x = to_tf32(v.x); v.y = to_tf32(v.y);
            v.z = to_tf32(v.z); v.w = to_tf32(v.w);
            *(float4*)(xs + r*XS_LD + q*4) = v;
        }
    }
    __syncthreads();

    const int br    = wrp >> 1;     // branch (warp-uniform)
    const int thalf = wrp & 1;      // t half
    const int dil   = 1 << br;      // 1,2,4,8
    const int jmin  = (br == 0) ? 6 : (br == 1) ? 4 : 0;  // first nonzero tap

    float acc[4][4][4];
    #pragma unroll
    for (int mt = 0; mt < 4; mt++)
        #pragma unroll
        for (int nt = 0; nt < 4; nt++)
            #pragma unroll
            for (int r = 0; r < 4; r++) acc[mt][nt][r] = 0.f;

    // ---- Stage B: per-warp conv GEMMs, weights streamed via LDG.128 ----
    {
        const float4* wf_br = (const float4*)g_wfrag + (size_t)br*9*512 + lane*2;
        for (int j = jmin; j < 9; j++) {
            const float4* wf = wf_br + j*512;
            const int off   = dil * (8 - j);
            const int arow0 = 64 + thalf*64 + g - off;

            #pragma unroll
            for (int ks = 0; ks < 8; ks++) {
                float4 bf0 = __ldg(wf + ks*64);
                float4 bf1 = __ldg(wf + ks*64 + 1);
                const int ci0 = ks * 8;
                uint32_t a[4][4];
                #pragma unroll
                for (int mt = 0; mt < 4; mt++) {
                    const uint32_t* xp = (const uint32_t*)xs + (arow0 + mt*16)*XS_LD + ci0 + tg;
                    a[mt][0] = xp[0];
                    a[mt][1] = xp[8*XS_LD];
                    a[mt][2] = xp[4];
                    a[mt][3] = xp[8*XS_LD + 4];
                }
                uint32_t bw[8];
                bw[0]=__float_as_uint(bf0.x); bw[1]=__float_as_uint(bf0.y);
                bw[2]=__float_as_uint(bf0.z); bw[3]=__float_as_uint(bf0.w);
                bw[4]=__float_as_uint(bf1.x); bw[5]=__float_as_uint(bf1.y);
                bw[6]=__float_as_uint(bf1.z); bw[7]=__float_as_uint(bf1.w);
                #pragma unroll
                for (int mt = 0; mt < 4; mt++)
                    #pragma unroll
                    for (int nt = 0; nt < 4; nt++)
                        mma8(acc[mt][nt], a[mt], bw + nt*2);
            }
        }
    }
    __syncthreads();   // all warps done reading xs before act overlays it

    // ---- bias + relu -> act smem (tf32) ----
    {
        #pragma unroll
        for (int nt = 0; nt < 4; nt++) {
            int c = br*32 + nt*8 + 2*tg;
            float2 bv = *(const float2*)(g_bcat + c);
            #pragma unroll
            for (int mt = 0; mt < 4; mt++) {
                int r0 = thalf*64 + mt*16 + g;
                float v0 = fmaxf(acc[mt][nt][0] + bv.x, 0.f);
                float v1 = fmaxf(acc[mt][nt][1] + bv.y, 0.f);
                float v2 = fmaxf(acc[mt][nt][2] + bv.x, 0.f);
                float v3 = fmaxf(acc[mt][nt][3] + bv.y, 0.f);
                *(float2*)(act + r0*ACT_LD + c)     = make_float2(to_tf32(v0), to_tf32(v1));
                *(float2*)(act + (r0+8)*ACT_LD + c) = make_float2(to_tf32(v2), to_tf32(v3));
            }
        }
    }
    __syncthreads();

    // ---- Stage C: out = relu_act @ w_out + b_out (128x128x128) ----
    const int mq = wrp >> 2;   // t half
    const int nq = wrp & 3;    // f quarter
    #pragma unroll
    for (int mt = 0; mt < 4; mt++)
        #pragma unroll
        for (int nt = 0; nt < 4; nt++)
            #pragma unroll
            for (int r = 0; r < 4; r++) acc[mt][nt][r] = 0.f;

    {
        const float4* wof = (const float4*)g_wofrag + (size_t)nq*16*64 + lane*2;
        #pragma unroll
        for (int ks = 0; ks < 16; ks++) {
            float4 bf0 = __ldg(wof + ks*64);
            float4 bf1 = __ldg(wof + ks*64 + 1);
            const int ci0 = ks * 8;
            uint32_t a[4][4];
            #pragma unroll
            for (int mt = 0; mt < 4; mt++) {
                const uint32_t* ap = (const uint32_t*)act + (mq*64 + mt*16 + g)*ACT_LD + ci0 + tg;
                a[mt][0] = ap[0];
                a[mt][1] = ap[8*ACT_LD];
                a[mt][2] = ap[4];
                a[mt][3] = ap[8*ACT_LD + 4];
            }
            uint32_t bw[8];
            bw[0]=__float_as_uint(bf0.x); bw[1]=__float_as_uint(bf0.y);
            bw[2]=__float_as_uint(bf0.z); bw[3]=__float_as_uint(bf0.w);
            bw[4]=__float_as_uint(bf1.x); bw[5]=__float_as_uint(bf1.y);
            bw[6]=__float_as_uint(bf1.z); bw[7]=__float_as_uint(bf1.w);
            #pragma unroll
            for (int mt = 0; mt < 4; mt++)
                #pragma unroll
                for (int nt = 0; nt < 4; nt++)
                    mma8(acc[mt][nt], a[mt], bw + nt*2);
        }
    }

    // ---- epilogue: + b_out, store ----
    {
        float* ob = out + ((size_t)b*8192 + t0) * 128;
        #pragma unroll
        for (int nt = 0; nt < 4; nt++) {
            int c = nq*32 + nt*8 + 2*tg;
            float2 bv = *(const float2*)(b_out + c);
            #pragma unroll
            for (int mt = 0; mt < 4; mt++) {
                int r0 = mq*64 + mt*16 + g;
                *(float2*)(ob + (size_t)r0*128 + c) =
                    make_float2(acc[mt][nt][0] + bv.x, acc[mt][nt][1] + bv.y);
                *(float2*)(ob + (size_t)(r0+8)*128 + c) =
                    make_float2(acc[mt][nt][2] + bv.x, acc[mt][nt][3] + bv.y);
            }
        }
    }
}

// ------------------------------ launcher ------------------------------------
extern "C" void kernel_launch(void* const* d_in, const int* in_sizes, int n_in,
                              void* d_out, int out_size) {
    const float* x     = (const float*)d_in[0];
    const float* w_s   = (const float*)d_in[1];
    const float* b_s   = (const float*)d_in[2];
    const float* w_m   = (const float*)d_in[3];
    const float* b_m   = (const float*)d_in[4];
    const float* w_l   = (const float*)d_in[5];
    const float* b_l   = (const float*)d_in[6];
    const float* w_xl  = (const float*)d_in[7];
    const float* b_xl  = (const float*)d_in[8];
    const float* w_out = (const float*)d_in[9];
    const float* b_out = (const float*)d_in[10];
    float* out = (float*)d_out;

    cudaFuncSetAttribute(tcn_kernel, cudaFuncAttributeMaxDynamicSharedMemorySize, SMEM_BYTES);

    prep_kernel<<<(CONV_WORDS + WO_WORDS + 255)/256, 256>>>(
        w_s, w_m, w_l, w_xl, b_s, b_m, b_l, b_xl, w_out);

    dim3 grid(8192 / 128, 16);   // (t-tiles, batch)
    tcn_kernel<<<grid, 256, SMEM_BYTES>>>(x, b_out, out);
}

// round 7
// speedup vs baseline: 2.8824x; 1.6176x over previous
#include <cuda_runtime.h>
#include <cuda_fp16.h>
#include <cstdint>

// ---------------------------------------------------------------------------
// StreamingMultiScaleTCN fused kernel, R7: fp16 m16n8k16 mma (same 10-bit
// mantissa as tf32 -> identical precision, 2x MAC/instr, half the LDS/LDG).
//
// Branches: br0 K=3,d=1  br1 K=5,d=2  br2 K=9,d=4  br3 K=9,d=8 (taps padded
// to 9; zero taps skipped). relu(y+b), concat(128), 1x1 proj w_out + b_out.
//
// Per CTA: one batch b, 128 timesteps.
//   A: x[t0-64..t0+128) x 64ch -> smem (fp16)            [syncthreads]
//   B: per-warp (branch, t-half) conv GEMMs m16n8k16.f16; B operands are
//      fragment-packed half2 streams (g_wfrag) via LDG.128, no barriers
//                                                         [syncthreads]
//   relu+bias -> act smem fp16 (overlays xs)              [syncthreads]
//   C: out = act @ w_out + b_out; w_out fragments via LDG.128
// ---------------------------------------------------------------------------

#define XW 36    // xs row stride in 32-bit words (72 halves); 36%32==4 -> (4g+tg) banks
#define AW 68    // act row stride in words (136 halves); 68%32==4

#define SMEM_WORDS (128 * AW)          // 8704 words >= 192*XW=6912 (overlay ok)
#define SMEM_BYTES (SMEM_WORDS * 4)    // 34816 B

#define CONV_WORDS (4*9*4*32*8)   // [br][tap][ks4][lane][8w] = 36864 half2-words
#define WO_WORDS   (4*8*32*8)     // [nq][ks8][lane][8w]      = 8192

__device__ __align__(16) uint32_t g_wfrag[CONV_WORDS];  // conv B-frags (half2)
__device__ __align__(16) uint32_t g_wofrag[WO_WORDS];   // w_out B-frags (half2)
__device__ float g_bcat[128];                           // concat branch biases

__device__ __forceinline__ uint32_t pack_h2(float a, float b) {
    __half2 h = __floats2half2_rn(a, b);
    return *reinterpret_cast<uint32_t*>(&h);
}

__device__ __forceinline__ void mma16(float* d, const uint32_t* a, const uint32_t* b) {
    asm volatile(
        "mma.sync.aligned.m16n8k16.row.col.f32.f16.f16.f32 "
        "{%0,%1,%2,%3}, {%4,%5,%6,%7}, {%8,%9}, {%0,%1,%2,%3};\n"
        : "+f"(d[0]), "+f"(d[1]), "+f"(d[2]), "+f"(d[3])
        : "r"(a[0]), "r"(a[1]), "r"(a[2]), "r"(a[3]),
          "r"(b[0]), "r"(b[1]));
}

// --------------------------- weight prep kernel -----------------------------
// m16n8k16 col-major B fragment: thread(g=lane>>2, tg=lane&3) word w8 in [0,8):
//   nt = w8>>1, wlo = w8&1; k0 = ks*16 + 2*tg + 8*wlo; packs (k0, k0+1);
//   out col c = nt*8 + g.
__global__ void prep_kernel(const float* __restrict__ w_s, const float* __restrict__ w_m,
                            const float* __restrict__ w_l, const float* __restrict__ w_xl,
                            const float* __restrict__ b_s, const float* __restrict__ b_m,
                            const float* __restrict__ b_l, const float* __restrict__ b_xl,
                            const float* __restrict__ w_out) {
    int idx = blockIdx.x * 256 + threadIdx.x;
    if (idx < CONV_WORDS) {
        int w8   = idx & 7;
        int lane = (idx >> 3) & 31;
        int ks   = (idx >> 8) & 3;
        int bj   = idx >> 10;          // br*9 + j
        int j    = bj % 9;
        int br   = bj / 9;
        int tg = lane & 3, g = lane >> 2;
        int k0 = ks*16 + 2*tg + 8*(w8 & 1);
        int c  = (w8 >> 1)*8 + g;
        float v0 = 0.f, v1 = 0.f;
        if      (br == 0) { if (j >= 6) { v0 = w_s [((j-6)*64 + k0)*32 + c];
                                          v1 = w_s [((j-6)*64 + k0+1)*32 + c]; } }
        else if (br == 1) { if (j >= 4) { v0 = w_m [((j-4)*64 + k0)*32 + c];
                                          v1 = w_m [((j-4)*64 + k0+1)*32 + c]; } }
        else if (br == 2) {               v0 = w_l [(j*64 + k0)*32 + c];
                                          v1 = w_l [(j*64 + k0+1)*32 + c]; }
        else              {               v0 = w_xl[(j*64 + k0)*32 + c];
                                          v1 = w_xl[(j*64 + k0+1)*32 + c]; }
        g_wfrag[idx] = pack_h2(v0, v1);
    } else if (idx < CONV_WORDS + WO_WORDS) {
        int k2   = idx - CONV_WORDS;
        int w8   = k2 & 7;
        int lane = (k2 >> 3) & 31;
        int ks   = (k2 >> 8) & 7;
        int nq   = k2 >> 11;
        int tg = lane & 3, g = lane >> 2;
        int k0 = ks*16 + 2*tg + 8*(w8 & 1);
        int f  = nq*32 + (w8 >> 1)*8 + g;
        g_wofrag[k2] = pack_h2(w_out[k0*128 + f], w_out[(k0+1)*128 + f]);
    }
    if (blockIdx.x == 0 && threadIdx.x < 128) {
        int i = threadIdx.x;
        const float* bsel = (i < 32) ? b_s : (i < 64) ? b_m : (i < 96) ? b_l : b_xl;
        g_bcat[i] = bsel[i & 31];
    }
}

// ------------------------------ main kernel ---------------------------------
__global__ __launch_bounds__(256, 2)
void tcn_kernel(const float* __restrict__ x,
                const float* __restrict__ b_out, float* __restrict__ out) {
    extern __shared__ uint32_t smem[];   // xs [192][XW] then act [128][AW]

    const int tid  = threadIdx.x;
    const int lane = tid & 31;
    const int wrp  = tid >> 5;
    const int g    = lane >> 2;   // 0..7
    const int tg   = lane & 3;    // 0..3
    const int b    = blockIdx.y;
    const int t0   = blockIdx.x * 128;

    // ---- Stage A: x tile (64-row causal halo) -> smem, fp16 ----
    {
        const float* xb = x + ((size_t)b * 8192) * 64;
        #pragma unroll 4
        for (int i = tid; i < 192*16; i += 256) {
            int r = i >> 4, q = i & 15;        // q indexes 4-channel groups
            int gt = t0 - 64 + r;
            float4 v = make_float4(0.f, 0.f, 0.f, 0.f);
            if (gt >= 0) v = *(const float4*)(xb + (size_t)gt*64 + q*4);
            uint2 h = make_uint2(pack_h2(v.x, v.y), pack_h2(v.z, v.w));
            *(uint2*)(smem + r*XW + q*2) = h;
        }
    }
    __syncthreads();

    const int br    = wrp >> 1;     // branch (warp-uniform)
    const int thalf = wrp & 1;      // t half
    const int dil   = 1 << br;      // 1,2,4,8
    const int jmin  = (br == 0) ? 6 : (br == 1) ? 4 : 0;

    float acc[4][4][4];
    #pragma unroll
    for (int mt = 0; mt < 4; mt++)
        #pragma unroll
        for (int nt = 0; nt < 4; nt++)
            #pragma unroll
            for (int r = 0; r < 4; r++) acc[mt][nt][r] = 0.f;

    // ---- Stage B: per-warp conv GEMMs (m16n8k16), weights via LDG.128 ----
    {
        const float4* wf_br = (const float4*)g_wfrag + (size_t)br*9*256 + lane*2;
        for (int j = jmin; j < 9; j++) {
            const float4* wf = wf_br + j*256;
            const int off   = dil * (8 - j);
            const int arow0 = 64 + thalf*64 + g - off;

            #pragma unroll
            for (int ks = 0; ks < 4; ks++) {
                float4 bf0 = __ldg(wf + ks*64);
                float4 bf1 = __ldg(wf + ks*64 + 1);
                uint32_t a[4][4];
                #pragma unroll
                for (int mt = 0; mt < 4; mt++) {
                    const uint32_t* xp = smem + (arow0 + mt*16)*XW + ks*8 + tg;
                    a[mt][0] = xp[0];
                    a[mt][1] = xp[8*XW];
                    a[mt][2] = xp[4];
                    a[mt][3] = xp[8*XW + 4];
                }
                uint32_t bw[8];
                bw[0]=__float_as_uint(bf0.x); bw[1]=__float_as_uint(bf0.y);
                bw[2]=__float_as_uint(bf0.z); bw[3]=__float_as_uint(bf0.w);
                bw[4]=__float_as_uint(bf1.x); bw[5]=__float_as_uint(bf1.y);
                bw[6]=__float_as_uint(bf1.z); bw[7]=__float_as_uint(bf1.w);
                #pragma unroll
                for (int mt = 0; mt < 4; mt++)
                    #pragma unroll
                    for (int nt = 0; nt < 4; nt++)
                        mma16(acc[mt][nt], a[mt], bw + nt*2);
            }
        }
    }
    __syncthreads();   // all warps done reading xs before act overlays it

    // ---- bias + relu -> act smem (fp16) ----
    {
        #pragma unroll
        for (int nt = 0; nt < 4; nt++) {
            int c = br*32 + nt*8 + 2*tg;              // even channel
            float2 bv = *(const float2*)(g_bcat + c);
            int cw = (c >> 1);                        // half2 word col
            #pragma unroll
            for (int mt = 0; mt < 4; mt++) {
                int r0 = thalf*64 + mt*16 + g;
                float v0 = fmaxf(acc[mt][nt][0] + bv.x, 0.f);
                float v1 = fmaxf(acc[mt][nt][1] + bv.y, 0.f);
                float v2 = fmaxf(acc[mt][nt][2] + bv.x, 0.f);
                float v3 = fmaxf(acc[mt][nt][3] + bv.y, 0.f);
                smem[r0*AW + cw]     = pack_h2(v0, v1);
                smem[(r0+8)*AW + cw] = pack_h2(v2, v3);
            }
        }
    }
    __syncthreads();

    // ---- Stage C: out = relu_act @ w_out + b_out (128x128x128) ----
    const int mq = wrp >> 2;   // t half
    const int nq = wrp & 3;    // f quarter
    #pragma unroll
    for (int mt = 0; mt < 4; mt++)
        #pragma unroll
        for (int nt = 0; nt < 4; nt++)
            #pragma unroll
            for (int r = 0; r < 4; r++) acc[mt][nt][r] = 0.f;

    {
        const float4* wof = (const float4*)g_wofrag + (size_t)nq*512 + lane*2;
        #pragma unroll
        for (int ks = 0; ks < 8; ks++) {
            float4 bf0 = __ldg(wof + ks*64);
            float4 bf1 = __ldg(wof + ks*64 + 1);
            uint32_t a[4][4];
            #pragma unroll
            for (int mt = 0; mt < 4; mt++) {
                const uint32_t* ap = smem + (mq*64 + mt*16 + g)*AW + ks*8 + tg;
                a[mt][0] = ap[0];
                a[mt][1] = ap[8*AW];
                a[mt][2] = ap[4];
                a[mt][3] = ap[8*AW + 4];
            }
            uint32_t bw[8];
            bw[0]=__float_as_uint(bf0.x); bw[1]=__float_as_uint(bf0.y);
            bw[2]=__float_as_uint(bf0.z); bw[3]=__float_as_uint(bf0.w);
            bw[4]=__float_as_uint(bf1.x); bw[5]=__float_as_uint(bf1.y);
            bw[6]=__float_as_uint(bf1.z); bw[7]=__float_as_uint(bf1.w);
            #pragma unroll
            for (int mt = 0; mt < 4; mt++)
                #pragma unroll
                for (int nt = 0; nt < 4; nt++)
                    mma16(acc[mt][nt], a[mt], bw + nt*2);
        }
    }

    // ---- epilogue: + b_out, store fp32 ----
    {
        float* ob = out + ((size_t)b*8192 + t0) * 128;
        #pragma unroll
        for (int nt = 0; nt < 4; nt++) {
            int c = nq*32 + nt*8 + 2*tg;
            float2 bv = *(const float2*)(b_out + c);
            #pragma unroll
            for (int mt = 0; mt < 4; mt++) {
                int r0 = mq*64 + mt*16 + g;
                *(float2*)(ob + (size_t)r0*128 + c) =
                    make_float2(acc[mt][nt][0] + bv.x, acc[mt][nt][1] + bv.y);
                *(float2*)(ob + (size_t)(r0+8)*128 + c) =
                    make_float2(acc[mt][nt][2] + bv.x, acc[mt][nt][3] + bv.y);
            }
        }
    }
}

// ------------------------------ launcher ------------------------------------
extern "C" void kernel_launch(void* const* d_in, const int* in_sizes, int n_in,
                              void* d_out, int out_size) {
    const float* x     = (const float*)d_in[0];
    const float* w_s   = (const float*)d_in[1];
    const float* b_s   = (const float*)d_in[2];
    const float* w_m   = (const float*)d_in[3];
    const float* b_m   = (const float*)d_in[4];
    const float* w_l   = (const float*)d_in[5];
    const float* b_l   = (const float*)d_in[6];
    const float* w_xl  = (const float*)d_in[7];
    const float* b_xl  = (const float*)d_in[8];
    const float* w_out = (const float*)d_in[9];
    const float* b_out = (const float*)d_in[10];
    float* out = (float*)d_out;

    cudaFuncSetAttribute(tcn_kernel, cudaFuncAttributeMaxDynamicSharedMemorySize, SMEM_BYTES);

    prep_kernel<<<(CONV_WORDS + WO_WORDS + 255)/256, 256>>>(
        w_s, w_m, w_l, w_xl, b_s, b_m, b_l, b_xl, w_out);

    dim3 grid(8192 / 128, 16);   // (t-tiles, batch)
    tcn_kernel<<<grid, 256, SMEM_BYTES>>>(x, b_out, out);
}

// round 8
// speedup vs baseline: 2.8837x; 1.0005x over previous
#include <cuda_runtime.h>
#include <cuda_fp16.h>
#include <cstdint>

// ---------------------------------------------------------------------------
// StreamingMultiScaleTCN fused kernel, R8: R7 + ldmatrix.x4 A-fragment loads
// (16 LDS.32 -> 4 LDSM.x4 per ks step) and uint4 weight loads.
//
// Branches: br0 K=3,d=1  br1 K=5,d=2  br2 K=9,d=4  br3 K=9,d=8 (zero taps
// skipped). relu(y+b), concat(128), 1x1 proj w_out + b_out.
//
// Per CTA: one batch b, 128 timesteps.
//   A: x[t0-64..t0+128) x 64ch -> smem (fp16)            [syncthreads]
//   B: per-warp (branch, t-half) conv GEMMs m16n8k16.f16; A via ldmatrix,
//      B via fragment-packed LDG.128 streams, no barriers [syncthreads]
//   relu+bias -> act smem fp16 (overlays xs)              [syncthreads]
//   C: out = act @ w_out + b_out (m16n8k16, ldmatrix A)
// ---------------------------------------------------------------------------

#define XW 36    // xs row stride in words (72 halves); 36%32==4 -> conflict-free
#define AW 68    // act row stride in words (136 halves); 68%32==4

#define SMEM_WORDS (128 * AW)          // 8704 >= 192*XW=6912 (overlay ok)
#define SMEM_BYTES (SMEM_WORDS * 4)    // 34816 B

#define CONV_WORDS (4*9*4*32*8)   // [br][tap][ks4][lane][8w] = 36864
#define WO_WORDS   (4*8*32*8)     // [nq][ks8][lane][8w]      = 8192

__device__ __align__(16) uint32_t g_wfrag[CONV_WORDS];  // conv B-frags (half2)
__device__ __align__(16) uint32_t g_wofrag[WO_WORDS];   // w_out B-frags (half2)
__device__ float g_bcat[128];                           // concat branch biases

__device__ __forceinline__ uint32_t pack_h2(float a, float b) {
    __half2 h = __floats2half2_rn(a, b);
    return *reinterpret_cast<uint32_t*>(&h);
}

__device__ __forceinline__ void mma16(float* d, const uint32_t* a, const uint32_t* b) {
    asm volatile(
        "mma.sync.aligned.m16n8k16.row.col.f32.f16.f16.f32 "
        "{%0,%1,%2,%3}, {%4,%5,%6,%7}, {%8,%9}, {%0,%1,%2,%3};\n"
        : "+f"(d[0]), "+f"(d[1]), "+f"(d[2]), "+f"(d[3])
        : "r"(a[0]), "r"(a[1]), "r"(a[2]), "r"(a[3]),
          "r"(b[0]), "r"(b[1]));
}

__device__ __forceinline__ void ldsm4(uint32_t* r, uint32_t saddr) {
    asm volatile(
        "ldmatrix.sync.aligned.m8n8.x4.shared.b16 {%0,%1,%2,%3}, [%4];\n"
        : "=r"(r[0]), "=r"(r[1]), "=r"(r[2]), "=r"(r[3]) : "r"(saddr));
}

// --------------------------- weight prep kernel -----------------------------
// m16n8k16 col-major B fragment: thread(g=lane>>2, tg=lane&3) word w8 in [0,8):
//   nt = w8>>1, wlo = w8&1; k0 = ks*16 + 2*tg + 8*wlo; packs (k0, k0+1);
//   out col c = nt*8 + g.
__global__ void prep_kernel(const float* __restrict__ w_s, const float* __restrict__ w_m,
                            const float* __restrict__ w_l, const float* __restrict__ w_xl,
                            const float* __restrict__ b_s, const float* __restrict__ b_m,
                            const float* __restrict__ b_l, const float* __restrict__ b_xl,
                            const float* __restrict__ w_out) {
    int idx = blockIdx.x * 256 + threadIdx.x;
    if (idx < CONV_WORDS) {
        int w8   = idx & 7;
        int lane = (idx >> 3) & 31;
        int ks   = (idx >> 8) & 3;
        int bj   = idx >> 10;          // br*9 + j
        int j    = bj % 9;
        int br   = bj / 9;
        int tg = lane & 3, g = lane >> 2;
        int k0 = ks*16 + 2*tg + 8*(w8 & 1);
        int c  = (w8 >> 1)*8 + g;
        float v0 = 0.f, v1 = 0.f;
        if      (br == 0) { if (j >= 6) { v0 = w_s [((j-6)*64 + k0)*32 + c];
                                          v1 = w_s [((j-6)*64 + k0+1)*32 + c]; } }
        else if (br == 1) { if (j >= 4) { v0 = w_m [((j-4)*64 + k0)*32 + c];
                                          v1 = w_m [((j-4)*64 + k0+1)*32 + c]; } }
        else if (br == 2) {               v0 = w_l [(j*64 + k0)*32 + c];
                                          v1 = w_l [(j*64 + k0+1)*32 + c]; }
        else              {               v0 = w_xl[(j*64 + k0)*32 + c];
                                          v1 = w_xl[(j*64 + k0+1)*32 + c]; }
        g_wfrag[idx] = pack_h2(v0, v1);
    } else if (idx < CONV_WORDS + WO_WORDS) {
        int k2   = idx - CONV_WORDS;
        int w8   = k2 & 7;
        int lane = (k2 >> 3) & 31;
        int ks   = (k2 >> 8) & 7;
        int nq   = k2 >> 11;
        int tg = lane & 3, g = lane >> 2;
        int k0 = ks*16 + 2*tg + 8*(w8 & 1);
        int f  = nq*32 + (w8 >> 1)*8 + g;
        g_wofrag[k2] = pack_h2(w_out[k0*128 + f], w_out[(k0+1)*128 + f]);
    }
    if (blockIdx.x == 0 && threadIdx.x < 128) {
        int i = threadIdx.x;
        const float* bsel = (i < 32) ? b_s : (i < 64) ? b_m : (i < 96) ? b_l : b_xl;
        g_bcat[i] = bsel[i & 31];
    }
}

// ------------------------------ main kernel ---------------------------------
__global__ __launch_bounds__(256, 2)
void tcn_kernel(const float* __restrict__ x,
                const float* __restrict__ b_out, float* __restrict__ out) {
    extern __shared__ uint32_t smem[];   // xs [192][XW] then act [128][AW]

    const int tid  = threadIdx.x;
    const int lane = tid & 31;
    const int wrp  = tid >> 5;
    const int g    = lane >> 2;   // 0..7
    const int tg   = lane & 3;    // 0..3
    const int b    = blockIdx.y;
    const int t0   = blockIdx.x * 128;

    const uint32_t smem_u32 = (uint32_t)__cvta_generic_to_shared(smem);
    // ldmatrix per-thread row/k-half offsets
    const int lrow = (lane & 7) + ((lane >> 3) & 1) * 8;  // row within 16
    const int lkw  = (lane >> 4) * 4;                     // +4 words for k8-15

    // ---- Stage A: x tile (64-row causal halo) -> smem, fp16 ----
    {
        const float* xb = x + ((size_t)b * 8192) * 64;
        #pragma unroll 4
        for (int i = tid; i < 192*16; i += 256) {
            int r = i >> 4, q = i & 15;
            int gt = t0 - 64 + r;
            float4 v = make_float4(0.f, 0.f, 0.f, 0.f);
            if (gt >= 0) v = *(const float4*)(xb + (size_t)gt*64 + q*4);
            uint2 h = make_uint2(pack_h2(v.x, v.y), pack_h2(v.z, v.w));
            *(uint2*)(smem + r*XW + q*2) = h;
        }
    }
    __syncthreads();

    const int br    = wrp >> 1;     // branch (warp-uniform)
    const int thalf = wrp & 1;      // t half
    const int dil   = 1 << br;      // 1,2,4,8
    const int jmin  = (br == 0) ? 6 : (br == 1) ? 4 : 0;

    float acc[4][4][4];
    #pragma unroll
    for (int mt = 0; mt < 4; mt++)
        #pragma unroll
        for (int nt = 0; nt < 4; nt++)
            #pragma unroll
            for (int r = 0; r < 4; r++) acc[mt][nt][r] = 0.f;

    // ---- Stage B: per-warp conv GEMMs (m16n8k16), A via ldmatrix ----
    {
        const uint4* wf_br = (const uint4*)g_wfrag + (size_t)br*9*256 + lane*2;
        for (int j = jmin; j < 9; j++) {
            const uint4* wf = wf_br + j*256;
            const int off   = dil * (8 - j);
            // per-thread ldmatrix base row (warp base + thread row)
            const int arowb = 64 + thalf*64 - off + lrow;

            #pragma unroll
            for (int ks = 0; ks < 4; ks++) {
                uint4 bf0 = __ldg(wf + ks*64);
                uint4 bf1 = __ldg(wf + ks*64 + 1);
                uint32_t a[4][4];
                #pragma unroll
                for (int mt = 0; mt < 4; mt++) {
                    uint32_t sa = smem_u32 +
                        ((arowb + mt*16)*XW + ks*8 + lkw) * 4;
                    ldsm4(a[mt], sa);
                }
                uint32_t bw[8] = {bf0.x, bf0.y, bf0.z, bf0.w,
                                  bf1.x, bf1.y, bf1.z, bf1.w};
                #pragma unroll
                for (int mt = 0; mt < 4; mt++)
                    #pragma unroll
                    for (int nt = 0; nt < 4; nt++)
                        mma16(acc[mt][nt], a[mt], bw + nt*2);
            }
        }
    }
    __syncthreads();   // all warps done reading xs before act overlays it

    // ---- bias + relu -> act smem (fp16) ----
    {
        #pragma unroll
        for (int nt = 0; nt < 4; nt++) {
            int c = br*32 + nt*8 + 2*tg;              // even channel
            float2 bv = *(const float2*)(g_bcat + c);
            int cw = (c >> 1);                        // half2 word col
            #pragma unroll
            for (int mt = 0; mt < 4; mt++) {
                int r0 = thalf*64 + mt*16 + g;
                float v0 = fmaxf(acc[mt][nt][0] + bv.x, 0.f);
                float v1 = fmaxf(acc[mt][nt][1] + bv.y, 0.f);
                float v2 = fmaxf(acc[mt][nt][2] + bv.x, 0.f);
                float v3 = fmaxf(acc[mt][nt][3] + bv.y, 0.f);
                smem[r0*AW + cw]     = pack_h2(v0, v1);
                smem[(r0+8)*AW + cw] = pack_h2(v2, v3);
            }
        }
    }
    __syncthreads();

    // ---- Stage C: out = relu_act @ w_out + b_out (128x128x128) ----
    const int mq = wrp >> 2;   // t half
    const int nq = wrp & 3;    // f quarter
    #pragma unroll
    for (int mt = 0; mt < 4; mt++)
        #pragma unroll
        for (int nt = 0; nt < 4; nt++)
            #pragma unroll
            for (int r = 0; r < 4; r++) acc[mt][nt][r] = 0.f;

    {
        const uint4* wof = (const uint4*)g_wofrag + (size_t)nq*512 + lane*2;
        const int crowb = mq*64 + lrow;
        #pragma unroll
        for (int ks = 0; ks < 8; ks++) {
            uint4 bf0 = __ldg(wof + ks*64);
            uint4 bf1 = __ldg(wof + ks*64 + 1);
            uint32_t a[4][4];
            #pragma unroll
            for (int mt = 0; mt < 4; mt++) {
                uint32_t sa = smem_u32 +
                    ((crowb + mt*16)*AW + ks*8 + lkw) * 4;
                ldsm4(a[mt], sa);
            }
            uint32_t bw[8] = {bf0.x, bf0.y, bf0.z, bf0.w,
                              bf1.x, bf1.y, bf1.z, bf1.w};
            #pragma unroll
            for (int mt = 0; mt < 4; mt++)
                #pragma unroll
                for (int nt = 0; nt < 4; nt++)
                    mma16(acc[mt][nt], a[mt], bw + nt*2);
        }
    }

    // ---- epilogue: + b_out, store fp32 ----
    {
        float* ob = out + ((size_t)b*8192 + t0) * 128;
        #pragma unroll
        for (int nt = 0; nt < 4; nt++) {
            int c = nq*32 + nt*8 + 2*tg;
            float2 bv = *(const float2*)(b_out + c);
            #pragma unroll
            for (int mt = 0; mt < 4; mt++) {
                int r0 = mq*64 + mt*16 + g;
                *(float2*)(ob + (size_t)r0*128 + c) =
                    make_float2(acc[mt][nt][0] + bv.x, acc[mt][nt][1] + bv.y);
                *(float2*)(ob + (size_t)(r0+8)*128 + c) =
                    make_float2(acc[mt][nt][2] + bv.x, acc[mt][nt][3] + bv.y);
            }
        }
    }
}

// ------------------------------ launcher ------------------------------------
extern "C" void kernel_launch(void* const* d_in, const int* in_sizes, int n_in,
                              void* d_out, int out_size) {
    const float* x     = (const float*)d_in[0];
    const float* w_s   = (const float*)d_in[1];
    const float* b_s   = (const float*)d_in[2];
    const float* w_m   = (const float*)d_in[3];
    const float* b_m   = (const float*)d_in[4];
    const float* w_l   = (const float*)d_in[5];
    const float* b_l   = (const float*)d_in[6];
    const float* w_xl  = (const float*)d_in[7];
    const float* b_xl  = (const float*)d_in[8];
    const float* w_out = (const float*)d_in[9];
    const float* b_out = (const float*)d_in[10];
    float* out = (float*)d_out;

    cudaFuncSetAttribute(tcn_kernel, cudaFuncAttributeMaxDynamicSharedMemorySize, SMEM_BYTES);

    prep_kernel<<<(CONV_WORDS + WO_WORDS + 255)/256, 256>>>(
        w_s, w_m, w_l, w_xl, b_s, b_m, b_l, b_xl, w_out);

    dim3 grid(8192 / 128, 16);   // (t-tiles, batch)
    tcn_kernel<<<grid, 256, SMEM_BYTES>>>(x, b_out, out);
}